// round 2
// baseline (speedup 1.0000x reference)
#include <cuda_runtime.h>

// Problem constants
#define NB 8          // batch
#define NL 512        // sequence length
#define NS 64         // spans per batch
#define NR 512        // NB*NS total span rows
#define D1 1024       // D
#define D2 2048       // 2*D

// ---------------------------------------------------------------------------
// Device scratch (no allocations allowed)
// ---------------------------------------------------------------------------
__device__ float g_gs [NR * D1];   // gathered start rows   (512, 1024)
__device__ float g_ge [NR * D1];   // gathered end rows     (512, 1024)
__device__ float g_t1s[NR * D2];   // relu(gs @ Ws1 + bs1)  (512, 2048)
__device__ float g_t1e[NR * D2];   // relu(ge @ We1 + be1)  (512, 2048)
__device__ float g_cat[NR * D2];   // relu([sp, ep])        (512, 2048)
__device__ float g_ent[NR * D2];   // cat @ Wo + bo         (512, 2048)
__device__ float g_hi [NR * D2];   // ent @ Wr1[:2048]      (512, 2048)
__device__ float g_hj [NR * D2];   // ent @ Wr1[2048:]      (512, 2048)

// ---------------------------------------------------------------------------
// Gather: pull only the 64 start/end rows per batch (8x less MLP work than ref)
// span is int32 (JAX x64 disabled -> int64 request materializes as int32).
// ---------------------------------------------------------------------------
__global__ void gather_kernel(const float* __restrict__ h,
                              const int* __restrict__ span)
{
    int bn = blockIdx.x;                 // 0..511  (b*64 + n)
    int b  = bn >> 6;
    int si = span[2 * bn + 0];
    int ei = span[2 * bn + 1];
    const float4* ps = (const float4*)(h + ((size_t)b * NL + (size_t)si) * D1);
    const float4* pe = (const float4*)(h + ((size_t)b * NL + (size_t)ei) * D1);
    float4* ds = (float4*)(g_gs + (size_t)bn * D1);
    float4* de = (float4*)(g_ge + (size_t)bn * D1);
    for (int t = threadIdx.x; t < D1 / 4; t += blockDim.x) {
        ds[t] = ps[t];
        de[t] = pe[t];
    }
}

// ---------------------------------------------------------------------------
// Generic fp32 SGEMM: C[M,N] = act(A[M,K] @ W[K,N] + bias)
// BM=BN=128, BK=8, 256 threads, 8x8 micro-tile.
// All M,N,K here are multiples of 128/8 -> no bounds checks.
// ---------------------------------------------------------------------------
#define BM 128
#define BN 128
#define BK 8
#define TM 8
#define TN 8

template<bool RELU>
__global__ __launch_bounds__(256)
void gemm_kernel(const float* __restrict__ A, const float* __restrict__ W,
                 const float* __restrict__ bias, float* __restrict__ C,
                 int M, int N, int K, int ldc)
{
    __shared__ float As[BK][BM];
    __shared__ float Bs[BK][BN];

    const int tid = threadIdx.x;
    const int tx  = tid & 15;
    const int ty  = tid >> 4;
    const int rowBase = blockIdx.y * BM;
    const int colBase = blockIdx.x * BN;

    const int l   = tid * 4;
    const int a_r = l >> 3;       // 0..127
    const int a_k = l & 7;        // 0 or 4
    const int b_k = l >> 7;       // 0..7
    const int b_c = l & 127;      // multiple of 4

    float acc[TM][TN];
#pragma unroll
    for (int i = 0; i < TM; i++)
#pragma unroll
        for (int j = 0; j < TN; j++) acc[i][j] = 0.f;

    const float* Aptr = A + (size_t)(rowBase + a_r) * K + a_k;
    const float* Wptr = W + (size_t)b_k * N + colBase + b_c;

    for (int k0 = 0; k0 < K; k0 += BK) {
        float4 av = *(const float4*)(Aptr + k0);
        As[a_k + 0][a_r] = av.x;
        As[a_k + 1][a_r] = av.y;
        As[a_k + 2][a_r] = av.z;
        As[a_k + 3][a_r] = av.w;
        *(float4*)&Bs[b_k][b_c] = *(const float4*)(Wptr + (size_t)k0 * N);
        __syncthreads();

#pragma unroll
        for (int kk = 0; kk < BK; kk++) {
            float4 a0 = *(const float4*)&As[kk][ty * TM];
            float4 a1 = *(const float4*)&As[kk][ty * TM + 4];
            float4 b0 = *(const float4*)&Bs[kk][tx * TN];
            float4 b1 = *(const float4*)&Bs[kk][tx * TN + 4];
            float a[TM] = {a0.x, a0.y, a0.z, a0.w, a1.x, a1.y, a1.z, a1.w};
            float bb[TN] = {b0.x, b0.y, b0.z, b0.w, b1.x, b1.y, b1.z, b1.w};
#pragma unroll
            for (int i = 0; i < TM; i++)
#pragma unroll
                for (int j = 0; j < TN; j++)
                    acc[i][j] = fmaf(a[i], bb[j], acc[i][j]);
        }
        __syncthreads();
    }

    float bj[TN];
#pragma unroll
    for (int j = 0; j < TN; j++)
        bj[j] = bias ? bias[colBase + tx * TN + j] : 0.f;

#pragma unroll
    for (int i = 0; i < TM; i++) {
        int r = rowBase + ty * TM + i;
        float* cp = C + (size_t)r * ldc + colBase + tx * TN;
#pragma unroll
        for (int j = 0; j < TN; j++) {
            float v = acc[i][j] + bj[j];
            if (RELU) v = fmaxf(v, 0.f);
            cp[j] = v;
        }
    }
}

// ---------------------------------------------------------------------------
// Final fused GEMM:
//   out[m, d] = relu(hi[b,i,:] + hj[b,j,:] + br1) @ Wr2 + br2
// with m = ((b*64 + i)*64 + j), M = 32768, K = 2048, N = 1024.
// The hidden tensor (256 MiB) is never materialized — A-tiles are generated
// on the fly from the L2-resident hi/hj (8 MB total).
// ---------------------------------------------------------------------------
__global__ __launch_bounds__(256)
void final_kernel(const float* __restrict__ br1,
                  const float* __restrict__ Wr2,
                  const float* __restrict__ br2,
                  float* __restrict__ out)
{
    __shared__ float As[BK][BM];
    __shared__ float Bs[BK][BN];

    const int tid = threadIdx.x;
    const int tx  = tid & 15;
    const int ty  = tid >> 4;
    const int rowBase = blockIdx.y * BM;     // flattened (b,i,j) rows
    const int colBase = blockIdx.x * BN;     // output feature d

    const int l   = tid * 4;
    const int a_r = l >> 3;
    const int a_k = l & 7;
    const int b_k = l >> 7;
    const int b_c = l & 127;

    const int m  = rowBase + a_r;
    const int b  = m >> 12;           // / 4096
    const int ii = (m >> 6) & 63;
    const int jj = m & 63;
    const float* hip = g_hi + (size_t)((b << 6) + ii) * D2 + a_k;
    const float* hjp = g_hj + (size_t)((b << 6) + jj) * D2 + a_k;
    const float* rp  = br1 + a_k;

    float acc[TM][TN];
#pragma unroll
    for (int i = 0; i < TM; i++)
#pragma unroll
        for (int j = 0; j < TN; j++) acc[i][j] = 0.f;

    const float* Wptr = Wr2 + (size_t)b_k * D1 + colBase + b_c;

    for (int k0 = 0; k0 < D2; k0 += BK) {
        float4 x = *(const float4*)(hip + k0);
        float4 y = *(const float4*)(hjp + k0);
        float4 r = *(const float4*)(rp + k0);
        As[a_k + 0][a_r] = fmaxf(x.x + y.x + r.x, 0.f);
        As[a_k + 1][a_r] = fmaxf(x.y + y.y + r.y, 0.f);
        As[a_k + 2][a_r] = fmaxf(x.z + y.z + r.z, 0.f);
        As[a_k + 3][a_r] = fmaxf(x.w + y.w + r.w, 0.f);
        *(float4*)&Bs[b_k][b_c] = *(const float4*)(Wptr + (size_t)k0 * D1);
        __syncthreads();

#pragma unroll
        for (int kk = 0; kk < BK; kk++) {
            float4 a0 = *(const float4*)&As[kk][ty * TM];
            float4 a1 = *(const float4*)&As[kk][ty * TM + 4];
            float4 b0 = *(const float4*)&Bs[kk][tx * TN];
            float4 b1 = *(const float4*)&Bs[kk][tx * TN + 4];
            float a[TM] = {a0.x, a0.y, a0.z, a0.w, a1.x, a1.y, a1.z, a1.w};
            float bb[TN] = {b0.x, b0.y, b0.z, b0.w, b1.x, b1.y, b1.z, b1.w};
#pragma unroll
            for (int i = 0; i < TM; i++)
#pragma unroll
                for (int j = 0; j < TN; j++)
                    acc[i][j] = fmaf(a[i], bb[j], acc[i][j]);
        }
        __syncthreads();
    }

    float bj[TN];
#pragma unroll
    for (int j = 0; j < TN; j++) bj[j] = br2[colBase + tx * TN + j];

#pragma unroll
    for (int i = 0; i < TM; i++) {
        int r = rowBase + ty * TM + i;
        float* cp = out + (size_t)r * D1 + colBase + tx * TN;
        float4 v0 = make_float4(acc[i][0] + bj[0], acc[i][1] + bj[1],
                                acc[i][2] + bj[2], acc[i][3] + bj[3]);
        float4 v1 = make_float4(acc[i][4] + bj[4], acc[i][5] + bj[5],
                                acc[i][6] + bj[6], acc[i][7] + bj[7]);
        *(float4*)(cp + 0) = v0;
        *(float4*)(cp + 4) = v1;
    }
}

// ---------------------------------------------------------------------------
// Launcher
// ---------------------------------------------------------------------------
extern "C" void kernel_launch(void* const* d_in, const int* in_sizes, int n_in,
                              void* d_out, int out_size)
{
    const float* h    = (const float*)d_in[0];
    const int*   span = (const int*)d_in[1];
    const float* Ws1 = (const float*)d_in[2];
    const float* bs1 = (const float*)d_in[3];
    const float* Ws2 = (const float*)d_in[4];
    const float* bs2 = (const float*)d_in[5];
    const float* We1 = (const float*)d_in[6];
    const float* be1 = (const float*)d_in[7];
    const float* We2 = (const float*)d_in[8];
    const float* be2 = (const float*)d_in[9];
    const float* Wo  = (const float*)d_in[10];
    const float* bo  = (const float*)d_in[11];
    const float* Wr1 = (const float*)d_in[12];
    const float* br1 = (const float*)d_in[13];
    const float* Wr2 = (const float*)d_in[14];
    const float* br2 = (const float*)d_in[15];
    float* out = (float*)d_out;

    float *gs, *ge, *t1s, *t1e, *cat, *ent, *hi, *hj;
    cudaGetSymbolAddress((void**)&gs,  g_gs);
    cudaGetSymbolAddress((void**)&ge,  g_ge);
    cudaGetSymbolAddress((void**)&t1s, g_t1s);
    cudaGetSymbolAddress((void**)&t1e, g_t1e);
    cudaGetSymbolAddress((void**)&cat, g_cat);
    cudaGetSymbolAddress((void**)&ent, g_ent);
    cudaGetSymbolAddress((void**)&hi,  g_hi);
    cudaGetSymbolAddress((void**)&hj,  g_hj);

    // 1) gather span rows
    gather_kernel<<<NR, 256>>>(h, span);

    // 2) first MLP layers (relu epilogue): (512,1024) @ (1024,2048)
    gemm_kernel<true><<<dim3(D2 / BN, NR / BM), 256>>>(gs, Ws1, bs1, t1s, NR, D2, D1, D2);
    gemm_kernel<true><<<dim3(D2 / BN, NR / BM), 256>>>(ge, We1, be1, t1e, NR, D2, D1, D2);

    // 3) second MLP layers + outer relu of concat, written into halves of cat:
    //    (512,2048) @ (2048,1024)
    gemm_kernel<true><<<dim3(D1 / BN, NR / BM), 256>>>(t1s, Ws2, bs2, cat,      NR, D1, D2, D2);
    gemm_kernel<true><<<dim3(D1 / BN, NR / BM), 256>>>(t1e, We2, be2, cat + D1, NR, D1, D2, D2);

    // 4) entity_reps = cat @ Wo + bo: (512,2048) @ (2048,2048)
    gemm_kernel<false><<<dim3(D2 / BN, NR / BM), 256>>>(cat, Wo, bo, ent, NR, D2, D2, D2);

    // 5) hi = ent @ Wr1[:2048], hj = ent @ Wr1[2048:]  (no bias)
    gemm_kernel<false><<<dim3(D2 / BN, NR / BM), 256>>>(ent, Wr1,                   nullptr, hi, NR, D2, D2, D2);
    gemm_kernel<false><<<dim3(D2 / BN, NR / BM), 256>>>(ent, Wr1 + (size_t)D2 * D2, nullptr, hj, NR, D2, D2, D2);

    // 6) fused final GEMM: out = relu(hi⊕hj + br1) @ Wr2 + br2
    //    M = 32768, N = 1024, K = 2048
    final_kernel<<<dim3(D1 / BN, (NB * NS * NS) / BM), 256>>>(br1, Wr2, br2, out);
}

// round 5
// speedup vs baseline: 2.0234x; 2.0234x over previous
#include <cuda_runtime.h>
#include <cuda_bf16.h>
#include <cstdint>

// Problem constants
#define NB 8          // batch
#define NL 512        // sequence length
#define NS 64         // spans per batch
#define NR 512        // NB*NS total span rows
#define D1 1024       // D
#define D2 2048       // 2*D

// ---------------------------------------------------------------------------
// Device scratch (no allocations allowed)
// ---------------------------------------------------------------------------
__device__ float g_gs [NR * D1];
__device__ float g_ge [NR * D1];
__device__ float g_t1s[NR * D2];
__device__ float g_t1e[NR * D2];
__device__ float g_cat[NR * D2];
__device__ float g_ent[NR * D2];
__device__ float g_hi [NR * D2];   // ent @ Wr1[:2048] + br1   (bias folded)
__device__ float g_hj [NR * D2];   // ent @ Wr1[2048:]
__device__ __nv_bfloat16 g_w2hi[D1 * D2];   // Wr2^T hi part  [n][k]
__device__ __nv_bfloat16 g_w2lo[D1 * D2];   // Wr2^T lo part  [n][k]

// ---------------------------------------------------------------------------
// PTX helpers (portable: sm_80-level features only; no 'a'-family instrs)
// ---------------------------------------------------------------------------
static __device__ __forceinline__ uint32_t smem_u32(const void* p) {
    uint32_t a;
    asm("{ .reg .u64 t; cvta.to.shared.u64 t, %1; cvt.u32.u64 %0, t; }"
        : "=r"(a) : "l"(p));
    return a;
}

static __device__ __forceinline__ void cp16(uint32_t dst, const void* src) {
    asm volatile("cp.async.cg.shared.global [%0], [%1], 16;"
                 :: "r"(dst), "l"(src));
}
#define CP_COMMIT() asm volatile("cp.async.commit_group;" ::: "memory")
#define CP_WAIT(n)  asm volatile("cp.async.wait_group %0;" :: "n"(n) : "memory")

static __device__ __forceinline__ void ldsm4(uint32_t r[4], uint32_t addr) {
    asm volatile("ldmatrix.sync.aligned.m8n8.x4.shared.b16 {%0,%1,%2,%3}, [%4];"
                 : "=r"(r[0]), "=r"(r[1]), "=r"(r[2]), "=r"(r[3]) : "r"(addr));
}

static __device__ __forceinline__ void mma16816(float c[4], const uint32_t a[4],
                                                uint32_t b0, uint32_t b1) {
    asm volatile(
        "mma.sync.aligned.m16n8k16.row.col.f32.bf16.bf16.f32 "
        "{%0,%1,%2,%3}, {%4,%5,%6,%7}, {%8,%9}, {%0,%1,%2,%3};"
        : "+f"(c[0]), "+f"(c[1]), "+f"(c[2]), "+f"(c[3])
        : "r"(a[0]), "r"(a[1]), "r"(a[2]), "r"(a[3]), "r"(b0), "r"(b1));
}

static __device__ __forceinline__ uint32_t pack_bf16(__nv_bfloat16 a, __nv_bfloat16 b) {
    __nv_bfloat162 t = __halves2bfloat162(a, b);
    return *(uint32_t*)&t;
}

// ---------------------------------------------------------------------------
// Gather
// ---------------------------------------------------------------------------
__global__ void gather_kernel(const float* __restrict__ h,
                              const int* __restrict__ span)
{
    int bn = blockIdx.x;
    int b  = bn >> 6;
    int si = span[2 * bn + 0];
    int ei = span[2 * bn + 1];
    const float4* ps = (const float4*)(h + ((size_t)b * NL + (size_t)si) * D1);
    const float4* pe = (const float4*)(h + ((size_t)b * NL + (size_t)ei) * D1);
    float4* ds = (float4*)(g_gs + (size_t)bn * D1);
    float4* de = (float4*)(g_ge + (size_t)bn * D1);
    for (int t = threadIdx.x; t < D1 / 4; t += blockDim.x) {
        ds[t] = ps[t];
        de[t] = pe[t];
    }
}

// ---------------------------------------------------------------------------
// Prep: Wr2 (2048 x 1024, row-major) -> transposed bf16 hi/lo (1024 x 2048)
// ---------------------------------------------------------------------------
__global__ void prep_wr2_kernel(const float* __restrict__ W)
{
    __shared__ float tile[32][33];
    int n0 = blockIdx.x * 32;
    int k0 = blockIdx.y * 32;
    int tx = threadIdx.x, ty = threadIdx.y;
    for (int i = ty; i < 32; i += 8)
        tile[i][tx] = W[(size_t)(k0 + i) * D1 + n0 + tx];
    __syncthreads();
    for (int i = ty; i < 32; i += 8) {
        float v = tile[tx][i];               // = Wr2[k0+tx][n0+i]
        __nv_bfloat16 hv = __float2bfloat16_rn(v);
        float lof = v - __bfloat162float(hv);
        size_t o = (size_t)(n0 + i) * D2 + k0 + tx;
        g_w2hi[o] = hv;
        g_w2lo[o] = __float2bfloat16_rn(lof);
    }
}

// ---------------------------------------------------------------------------
// Generic fp32 SGEMM (z-batched dual)
// ---------------------------------------------------------------------------
#define BM 128
#define BN 128
#define BK 8
#define TM 8
#define TN 8

template<bool RELU>
__global__ __launch_bounds__(256)
void gemm_dual_kernel(const float* __restrict__ A0, const float* __restrict__ A1,
                      const float* __restrict__ W0, const float* __restrict__ W1,
                      const float* __restrict__ bias0, const float* __restrict__ bias1,
                      float* __restrict__ C0, float* __restrict__ C1,
                      int N, int K, int ldc)
{
    const float* A    = blockIdx.z ? A1 : A0;
    const float* W    = blockIdx.z ? W1 : W0;
    const float* bias = blockIdx.z ? bias1 : bias0;
    float*       C    = blockIdx.z ? C1 : C0;

    __shared__ float As[BK][BM];
    __shared__ float Bs[BK][BN];

    const int tid = threadIdx.x;
    const int tx  = tid & 15;
    const int ty  = tid >> 4;
    const int rowBase = blockIdx.y * BM;
    const int colBase = blockIdx.x * BN;

    const int l   = tid * 4;
    const int a_r = l >> 3;
    const int a_k = l & 7;
    const int b_k = l >> 7;
    const int b_c = l & 127;

    float acc[TM][TN];
#pragma unroll
    for (int i = 0; i < TM; i++)
#pragma unroll
        for (int j = 0; j < TN; j++) acc[i][j] = 0.f;

    const float* Aptr = A + (size_t)(rowBase + a_r) * K + a_k;
    const float* Wptr = W + (size_t)b_k * N + colBase + b_c;

    for (int k0 = 0; k0 < K; k0 += BK) {
        float4 av = *(const float4*)(Aptr + k0);
        As[a_k + 0][a_r] = av.x;
        As[a_k + 1][a_r] = av.y;
        As[a_k + 2][a_r] = av.z;
        As[a_k + 3][a_r] = av.w;
        *(float4*)&Bs[b_k][b_c] = *(const float4*)(Wptr + (size_t)k0 * N);
        __syncthreads();

#pragma unroll
        for (int kk = 0; kk < BK; kk++) {
            float4 a0 = *(const float4*)&As[kk][ty * TM];
            float4 a1 = *(const float4*)&As[kk][ty * TM + 4];
            float4 b0 = *(const float4*)&Bs[kk][tx * TN];
            float4 b1 = *(const float4*)&Bs[kk][tx * TN + 4];
            float a[TM] = {a0.x, a0.y, a0.z, a0.w, a1.x, a1.y, a1.z, a1.w};
            float bb[TN] = {b0.x, b0.y, b0.z, b0.w, b1.x, b1.y, b1.z, b1.w};
#pragma unroll
            for (int i = 0; i < TM; i++)
#pragma unroll
                for (int j = 0; j < TN; j++)
                    acc[i][j] = fmaf(a[i], bb[j], acc[i][j]);
        }
        __syncthreads();
    }

    float bj[TN];
#pragma unroll
    for (int j = 0; j < TN; j++)
        bj[j] = bias ? bias[colBase + tx * TN + j] : 0.f;

#pragma unroll
    for (int i = 0; i < TM; i++) {
        int r = rowBase + ty * TM + i;
        float* cp = C + (size_t)r * ldc + colBase + tx * TN;
#pragma unroll
        for (int j = 0; j < TN; j++) {
            float v = acc[i][j] + bj[j];
            if (RELU) v = fmaxf(v, 0.f);
            cp[j] = v;
        }
    }
}

// ---------------------------------------------------------------------------
// Final GEMM on HMMA (mma.sync bf16, 3-term split, fp32 accum)
//   out[m,n] = relu(hi'[b,i,:] + hj[b,j,:]) @ Wr2 + br2     (br1 folded in hi')
//   m = ((b*64+i)*64+j), M=32768, K=2048, N=1024
// CTA tile 128x128, K-chunk 32, double-buffered SMEM (padded stride 80B rows).
// ---------------------------------------------------------------------------
#define KC   32
#define NC   (D2 / KC)        // 64 chunks
#define RSTR 80               // bytes per SMEM row (40 bf16, padded)
#define AHO  0
#define ALO_ 10240
#define BHO  20480
#define BLO_ 30720
#define STG  40960            // bytes per stage
#define FINAL_SMEM (2 * STG)  // 81920

__global__ __launch_bounds__(256)
void final_mma_kernel(const float* __restrict__ br2, float* __restrict__ out)
{
    extern __shared__ char smem[];
    const uint32_t sb = smem_u32(smem);
    const int tid  = threadIdx.x;
    const int lane = tid & 31;
    const int wid  = tid >> 5;
    const int wm   = wid >> 2;     // 0..1  (64 rows each)
    const int wn   = wid & 3;      // 0..3  (32 cols each)
    const int colBase = blockIdx.x * 128;
    const int rowBase = blockIdx.y * 128;

    // ---- fill mapping: 256 threads -> 128 rows x 2 k-halves of 16 ----
    const int fr = tid >> 1;            // 0..127
    const int fk = (tid & 1) << 4;      // 0 or 16
    const int m  = rowBase + fr;
    const int bI = m >> 12, iI = (m >> 6) & 63, jI = m & 63;
    const float* hiRow = g_hi + (size_t)((bI << 6) + iI) * D2;
    const float* hjRow = g_hj + (size_t)((bI << 6) + jI) * D2;
    const __nv_bfloat16* bhRow = g_w2hi + (size_t)(colBase + fr) * D2;
    const __nv_bfloat16* blRow = g_w2lo + (size_t)(colBase + fr) * D2;
    const uint32_t fillOff = (uint32_t)(fr * RSTR + fk * 2);

    float acc[4][4][4];
#pragma unroll
    for (int a = 0; a < 4; a++)
#pragma unroll
        for (int b = 0; b < 4; b++)
#pragma unroll
            for (int c = 0; c < 4; c++) acc[a][b][c] = 0.f;

    // ---- stage fill ----
    auto fill_stage = [&](int c) {
        const int st = (c & 1) * STG;
        const int k0 = c * KC;
        // B: cp.async straight copies (16B x2 per matrix)
        {
            uint32_t d = sb + BHO + st + fillOff;
            cp16(d,      bhRow + k0 + fk);
            cp16(d + 16, bhRow + k0 + fk + 8);
            d = sb + BLO_ + st + fillOff;
            cp16(d,      blRow + k0 + fk);
            cp16(d + 16, blRow + k0 + fk + 8);
        }
        // A: on-the-fly relu(hi'+hj) split to bf16 hi/lo
        const float4* xp = (const float4*)(hiRow + k0 + fk);
        const float4* yp = (const float4*)(hjRow + k0 + fk);
        uint32_t ah[8], al[8];
#pragma unroll
        for (int q = 0; q < 4; q++) {
            float4 x = xp[q], y = yp[q];
            float v0 = fmaxf(x.x + y.x, 0.f);
            float v1 = fmaxf(x.y + y.y, 0.f);
            float v2 = fmaxf(x.z + y.z, 0.f);
            float v3 = fmaxf(x.w + y.w, 0.f);
            __nv_bfloat16 h0 = __float2bfloat16_rn(v0);
            __nv_bfloat16 h1 = __float2bfloat16_rn(v1);
            __nv_bfloat16 h2 = __float2bfloat16_rn(v2);
            __nv_bfloat16 h3 = __float2bfloat16_rn(v3);
            ah[2 * q + 0] = pack_bf16(h0, h1);
            ah[2 * q + 1] = pack_bf16(h2, h3);
            al[2 * q + 0] = pack_bf16(__float2bfloat16_rn(v0 - __bfloat162float(h0)),
                                      __float2bfloat16_rn(v1 - __bfloat162float(h1)));
            al[2 * q + 1] = pack_bf16(__float2bfloat16_rn(v2 - __bfloat162float(h2)),
                                      __float2bfloat16_rn(v3 - __bfloat162float(h3)));
        }
        char* da = smem + AHO + st + fillOff;
        *(uint4*)(da)      = make_uint4(ah[0], ah[1], ah[2], ah[3]);
        *(uint4*)(da + 16) = make_uint4(ah[4], ah[5], ah[6], ah[7]);
        char* dl = smem + ALO_ + st + fillOff;
        *(uint4*)(dl)      = make_uint4(al[0], al[1], al[2], al[3]);
        *(uint4*)(dl + 16) = make_uint4(al[4], al[5], al[6], al[7]);
    };

    // ---- ldmatrix base addresses (per-thread) ----
    // A frag: row = tile + (lane&15), k-offset = (lane>>4)*8
    const uint32_t aOff = (uint32_t)((wm * 64 + (lane & 15)) * RSTR + ((lane >> 4) * 8) * 2);
    // B frag: row(n) = tile + (lane&7) + (lane>>4)*8, k-offset = ((lane>>3)&1)*8
    const uint32_t bOff = (uint32_t)((wn * 32 + (lane & 7) + ((lane >> 4) & 1) * 8) * RSTR
                                     + (((lane >> 3) & 1) * 8) * 2);

    // ---- prologue ----
    fill_stage(0);
    CP_COMMIT();

    for (int c = 0; c < NC; c++) {
        if (c + 1 < NC) {
            fill_stage(c + 1);
            CP_COMMIT();
            CP_WAIT(1);
        } else {
            CP_WAIT(0);
        }
        __syncthreads();   // stage c fully visible

        const int st = (c & 1) * STG;
        const uint32_t aH = sb + AHO + st + aOff;
        const uint32_t aL = sb + ALO_ + st + aOff;
        const uint32_t bH = sb + BHO + st + bOff;
        const uint32_t bL = sb + BLO_ + st + bOff;

#pragma unroll
        for (int ks = 0; ks < KC; ks += 16) {
            uint32_t ah[4][4], al4[4][4], bh[2][4], bl[2][4];
#pragma unroll
            for (int mt = 0; mt < 4; mt++) {
                ldsm4(ah[mt],  aH + mt * (16 * RSTR) + ks * 2);
                ldsm4(al4[mt], aL + mt * (16 * RSTR) + ks * 2);
            }
#pragma unroll
            for (int np = 0; np < 2; np++) {
                ldsm4(bh[np], bH + np * (16 * RSTR) + ks * 2);
                ldsm4(bl[np], bL + np * (16 * RSTR) + ks * 2);
            }
#pragma unroll
            for (int mt = 0; mt < 4; mt++) {
#pragma unroll
                for (int nt = 0; nt < 4; nt++) {
                    const int np = nt >> 1, h = (nt & 1) * 2;
                    mma16816(acc[mt][nt], ah[mt],  bh[np][h], bh[np][h + 1]);
                    mma16816(acc[mt][nt], ah[mt],  bl[np][h], bl[np][h + 1]);
                    mma16816(acc[mt][nt], al4[mt], bh[np][h], bh[np][h + 1]);
                }
            }
        }
        __syncthreads();   // readers done before refill of this stage
    }

    // ---- epilogue: acc -> out (+br2) ----
#pragma unroll
    for (int mt = 0; mt < 4; mt++) {
        const int r0 = rowBase + wm * 64 + mt * 16 + (lane >> 2);
#pragma unroll
        for (int nt = 0; nt < 4; nt++) {
            const int col = colBase + wn * 32 + nt * 8 + (lane & 3) * 2;
            const float b0 = br2[col], b1 = br2[col + 1];
            float2 v01 = make_float2(acc[mt][nt][0] + b0, acc[mt][nt][1] + b1);
            float2 v23 = make_float2(acc[mt][nt][2] + b0, acc[mt][nt][3] + b1);
            *(float2*)(out + (size_t)r0 * D1 + col)       = v01;
            *(float2*)(out + (size_t)(r0 + 8) * D1 + col) = v23;
        }
    }
}

// ---------------------------------------------------------------------------
// Launcher
// ---------------------------------------------------------------------------
extern "C" void kernel_launch(void* const* d_in, const int* in_sizes, int n_in,
                              void* d_out, int out_size)
{
    const float* h    = (const float*)d_in[0];
    const int*   span = (const int*)d_in[1];
    const float* Ws1 = (const float*)d_in[2];
    const float* bs1 = (const float*)d_in[3];
    const float* Ws2 = (const float*)d_in[4];
    const float* bs2 = (const float*)d_in[5];
    const float* We1 = (const float*)d_in[6];
    const float* be1 = (const float*)d_in[7];
    const float* We2 = (const float*)d_in[8];
    const float* be2 = (const float*)d_in[9];
    const float* Wo  = (const float*)d_in[10];
    const float* bo  = (const float*)d_in[11];
    const float* Wr1 = (const float*)d_in[12];
    const float* br1 = (const float*)d_in[13];
    const float* Wr2 = (const float*)d_in[14];
    const float* br2 = (const float*)d_in[15];
    float* out = (float*)d_out;

    float *gs, *ge, *t1s, *t1e, *cat, *ent, *hi, *hj;
    cudaGetSymbolAddress((void**)&gs,  g_gs);
    cudaGetSymbolAddress((void**)&ge,  g_ge);
    cudaGetSymbolAddress((void**)&t1s, g_t1s);
    cudaGetSymbolAddress((void**)&t1e, g_t1e);
    cudaGetSymbolAddress((void**)&cat, g_cat);
    cudaGetSymbolAddress((void**)&ent, g_ent);
    cudaGetSymbolAddress((void**)&hi,  g_hi);
    cudaGetSymbolAddress((void**)&hj,  g_hj);

    cudaFuncSetAttribute(final_mma_kernel,
                         cudaFuncAttributeMaxDynamicSharedMemorySize, FINAL_SMEM);

    // 0) prep: transpose + bf16-split Wr2 (independent)
    prep_wr2_kernel<<<dim3(D1 / 32, D2 / 32), dim3(32, 8)>>>(Wr2);

    // 1) gather span rows
    gather_kernel<<<NR, 256>>>(h, span);

    // 2) layer 1 (s & e batched): (512,1024)@(1024,2048), relu
    gemm_dual_kernel<true><<<dim3(D2 / BN, NR / BM, 2), 256>>>(
        gs, ge, Ws1, We1, bs1, be1, t1s, t1e, D2, D1, D2);

    // 3) layer 2 (s & e batched) + concat relu: (512,2048)@(2048,1024)
    gemm_dual_kernel<true><<<dim3(D1 / BN, NR / BM, 2), 256>>>(
        t1s, t1e, Ws2, We2, bs2, be2, cat, cat + D1, D1, D2, D2);

    // 4) entity_reps = cat @ Wo + bo: (512,2048)@(2048,2048)
    gemm_dual_kernel<false><<<dim3(D2 / BN, NR / BM, 1), 256>>>(
        cat, cat, Wo, Wo, bo, bo, ent, ent, D2, D2, D2);

    // 5) hi' = ent@Wr1a + br1 (bias folded!), hj = ent@Wr1b
    gemm_dual_kernel<false><<<dim3(D2 / BN, NR / BM, 2), 256>>>(
        ent, ent, Wr1, Wr1 + (size_t)D2 * D2, br1, nullptr, hi, hj, D2, D2, D2);

    // 6) final fused GEMM on tensor cores (HMMA): M=32768, N=1024, K=2048
    final_mma_kernel<<<dim3(D1 / 128, (NB * NS * NS) / 128), 256, FINAL_SMEM>>>(
        br2, out);
}